// round 1
// baseline (speedup 1.0000x reference)
#include <cuda_runtime.h>
#include <math.h>

#define EMB   1024
#define HD    64
#define NH    16
#define SEQ   2048
#define BATCH 2
#define MROWS (BATCH*SEQ)          // 4096
#define QKV_ELEMS (BATCH*NH*SEQ*HD)

// ---- scratch (allocation-free: __device__ globals) ----
__device__ float g_Q[QKV_ELEMS];
__device__ float g_K[QKV_ELEMS];
__device__ float g_V[QKV_ELEMS];
__device__ float g_O[QKV_ELEMS];
__device__ float g_partial[NH * 16];
__device__ float g_scale[NH];
__device__ float g_bias[EMB];

// ============================================================
// Kernel 1: QKV projection GEMM.
// C[4096,1024] = X[4096,1024] @ W + bias, W logical [E, H*hd] stored as [H,E,hd].
// Output written in [B,H,T,hd] layout. blockIdx.z in {0,1,2} = Q,K,V.
// Tiles: BM=BN=128, BK=16, 256 threads, 8x8 per thread (2x2 quadrants of 4).
// ============================================================
__global__ __launch_bounds__(256)
void qkv_gemm(const float* __restrict__ X,
              const float* __restrict__ Wq, const float* __restrict__ bq,
              const float* __restrict__ Wk, const float* __restrict__ bk,
              const float* __restrict__ Wv, const float* __restrict__ bv)
{
    const int z = blockIdx.z;
    const float* W    = (z == 0) ? Wq : (z == 1) ? Wk : Wv;
    const float* bias = (z == 0) ? bq : (z == 1) ? bk : bv;
    float* OUT        = (z == 0) ? g_Q : (z == 1) ? g_K : g_V;

    __shared__ float As[16][128];   // k-major (transposed A tile)
    __shared__ float Bs[16][128];

    const int m0  = blockIdx.y * 128;
    const int n0  = blockIdx.x * 128;
    const int tid = threadIdx.x;
    const int tx  = tid & 15;
    const int ty  = tid >> 4;

    float acc[8][8];
    #pragma unroll
    for (int i = 0; i < 8; i++)
        #pragma unroll
        for (int j = 0; j < 8; j++) acc[i][j] = 0.f;

    for (int k0 = 0; k0 < EMB; k0 += 16) {
        // load A tile (128 rows x 16 k), transpose into As[k][m]
        #pragma unroll
        for (int i = 0; i < 2; i++) {
            int f    = tid + i * 256;          // float4 id, 512 total
            int arow = f >> 2;
            int ac   = (f & 3) * 4;
            float4 v = *(const float4*)&X[(m0 + arow) * EMB + k0 + ac];
            As[ac + 0][arow] = v.x;
            As[ac + 1][arow] = v.y;
            As[ac + 2][arow] = v.z;
            As[ac + 3][arow] = v.w;
        }
        // load B tile (16 k x 128 cols); W element (d, c=(h,e)) at h*E*hd + d*hd + e
        #pragma unroll
        for (int i = 0; i < 2; i++) {
            int f    = tid + i * 256;
            int brow = f >> 5;
            int bc   = (f & 31) * 4;
            int c    = n0 + bc;
            int h    = c >> 6;
            int e    = c & 63;
            float4 v = *(const float4*)&W[h * (EMB * HD) + (k0 + brow) * HD + e];
            *(float4*)&Bs[brow][bc] = v;
        }
        __syncthreads();

        #pragma unroll
        for (int k = 0; k < 16; k++) {
            float a[8], b[8];
            #pragma unroll
            for (int i = 0; i < 4; i++) {
                a[i]     = As[k][ty * 4 + i];
                a[i + 4] = As[k][64 + ty * 4 + i];
                b[i]     = Bs[k][tx * 4 + i];
                b[i + 4] = Bs[k][64 + tx * 4 + i];
            }
            #pragma unroll
            for (int i = 0; i < 8; i++)
                #pragma unroll
                for (int j = 0; j < 8; j++)
                    acc[i][j] += a[i] * b[j];
        }
        __syncthreads();
    }

    // epilogue: remap (r,c) -> [B,H,T,hd], add bias (bias linear in c)
    #pragma unroll
    for (int i = 0; i < 8; i++) {
        int r  = m0 + ((i < 4) ? (ty * 4 + i) : (64 + ty * 4 + (i - 4)));
        int bb = r >> 11;
        int t  = r & 2047;
        #pragma unroll
        for (int j = 0; j < 8; j++) {
            int c = n0 + ((j < 4) ? (tx * 4 + j) : (64 + tx * 4 + (j - 4)));
            int h = c >> 6;
            int e = c & 63;
            OUT[((bb * NH + h) * SEQ + t) * HD + e] = acc[i][j] + bias[c];
        }
    }
}

// ============================================================
// Kernel 2: flash attention per (b,h). 64-row Q blocks, 64-col KV tiles.
// smem operand tiles stored k-major; P tile reuses the K buffer.
// ============================================================
__global__ __launch_bounds__(256)
void attn_kernel(const float* __restrict__ mask)
{
    __shared__ float Qs [64][64];   // [e][m]
    __shared__ float KPs[64][64];   // K as [e][s], then P as [r][s]
    __shared__ float Vs [64][64];   // [s][e]

    const int mblk = blockIdx.x;    // 0..31
    const int h    = blockIdx.y;
    const int b    = blockIdx.z;
    const int tid  = threadIdx.x;
    const int tx   = tid & 15;
    const int ty   = tid >> 4;

    const float* Q = g_Q + (size_t)(b * NH + h) * SEQ * HD;
    const float* K = g_K + (size_t)(b * NH + h) * SEQ * HD;
    const float* V = g_V + (size_t)(b * NH + h) * SEQ * HD;
    float*       O = g_O + (size_t)(b * NH + h) * SEQ * HD;

    const int t0 = mblk * 64;

    // load Q tile transposed: Qs[e][m]
    #pragma unroll
    for (int i = 0; i < 4; i++) {
        int f   = tid + i * 256;          // 1024 float4
        int row = f >> 4;                 // 0..63 (query row)
        int c   = (f & 15) * 4;           // 0..60 (head dim)
        float4 v = *(const float4*)&Q[(t0 + row) * HD + c];
        Qs[c + 0][row] = v.x;
        Qs[c + 1][row] = v.y;
        Qs[c + 2][row] = v.z;
        Qs[c + 3][row] = v.w;
    }

    float m_i[4], l_i[4], o[4][4];
    #pragma unroll
    for (int i = 0; i < 4; i++) {
        m_i[i] = -INFINITY;
        l_i[i] = 0.f;
        #pragma unroll
        for (int j = 0; j < 4; j++) o[i][j] = 0.f;
    }

    for (int s0 = 0; s0 < SEQ; s0 += 64) {
        __syncthreads();   // previous PV done (and Q visible on first iter)

        // load K transposed into KPs[e][s], V direct into Vs[s][e]
        #pragma unroll
        for (int i = 0; i < 4; i++) {
            int f   = tid + i * 256;
            int row = f >> 4;
            int c   = (f & 15) * 4;
            float4 kv = *(const float4*)&K[(s0 + row) * HD + c];
            KPs[c + 0][row] = kv.x;
            KPs[c + 1][row] = kv.y;
            KPs[c + 2][row] = kv.z;
            KPs[c + 3][row] = kv.w;
            float4 vv = *(const float4*)&V[(s0 + row) * HD + c];
            *(float4*)&Vs[row][c] = vv;
        }
        __syncthreads();

        // S = Q K^T  (per-thread 4x4: rows ty*4+i, cols tx*4+j)
        float sc[4][4];
        #pragma unroll
        for (int i = 0; i < 4; i++)
            #pragma unroll
            for (int j = 0; j < 4; j++) sc[i][j] = 0.f;

        #pragma unroll 8
        for (int k = 0; k < 64; k++) {
            float4 av = *(const float4*)&Qs [k][ty * 4];
            float4 bv = *(const float4*)&KPs[k][tx * 4];
            float a[4] = {av.x, av.y, av.z, av.w};
            float bb2[4] = {bv.x, bv.y, bv.z, bv.w};
            #pragma unroll
            for (int i = 0; i < 4; i++)
                #pragma unroll
                for (int j = 0; j < 4; j++)
                    sc[i][j] += a[i] * bb2[j];
        }

        // scale + mask
        #pragma unroll
        for (int i = 0; i < 4; i++) {
            const float* mrow = &mask[(size_t)(t0 + ty * 4 + i) * SEQ + s0 + tx * 4];
            #pragma unroll
            for (int j = 0; j < 4; j++)
                sc[i][j] = sc[i][j] * 0.125f + mrow[j];
        }

        // online softmax (row stats replicated across the 16-lane tx group)
        #pragma unroll
        for (int i = 0; i < 4; i++) {
            float rm = fmaxf(fmaxf(sc[i][0], sc[i][1]), fmaxf(sc[i][2], sc[i][3]));
            #pragma unroll
            for (int off = 1; off < 16; off <<= 1)
                rm = fmaxf(rm, __shfl_xor_sync(0xffffffffu, rm, off));
            float mnew = fmaxf(m_i[i], rm);
            float corr = __expf(m_i[i] - mnew);
            float rs = 0.f;
            #pragma unroll
            for (int j = 0; j < 4; j++) {
                float p = __expf(sc[i][j] - mnew);
                sc[i][j] = p;
                rs += p;
            }
            #pragma unroll
            for (int off = 1; off < 16; off <<= 1)
                rs += __shfl_xor_sync(0xffffffffu, rs, off);
            l_i[i] = l_i[i] * corr + rs;
            m_i[i] = mnew;
            #pragma unroll
            for (int j = 0; j < 4; j++) o[i][j] *= corr;
        }

        __syncthreads();   // all reads of KPs-as-K complete

        // store P into KPs as [r][s]
        #pragma unroll
        for (int i = 0; i < 4; i++)
            #pragma unroll
            for (int j = 0; j < 4; j++)
                KPs[ty * 4 + i][tx * 4 + j] = sc[i][j];
        __syncthreads();

        // O += P V
        #pragma unroll 8
        for (int s = 0; s < 64; s++) {
            float4 vv = *(const float4*)&Vs[s][tx * 4];
            float v4[4] = {vv.x, vv.y, vv.z, vv.w};
            float p0 = KPs[ty * 4 + 0][s];
            float p1 = KPs[ty * 4 + 1][s];
            float p2 = KPs[ty * 4 + 2][s];
            float p3 = KPs[ty * 4 + 3][s];
            #pragma unroll
            for (int j = 0; j < 4; j++) {
                o[0][j] += p0 * v4[j];
                o[1][j] += p1 * v4[j];
                o[2][j] += p2 * v4[j];
                o[3][j] += p3 * v4[j];
            }
        }
    }

    // finalize and write out (raw O; norm folded in later)
    #pragma unroll
    for (int i = 0; i < 4; i++) {
        float inv = 1.f / l_i[i];
        int t = t0 + ty * 4 + i;
        #pragma unroll
        for (int j = 0; j < 4; j++)
            O[t * HD + tx * 4 + j] = o[i][j] * inv;
    }
}

// ============================================================
// Kernel 3: per-head norm partial sums (deterministic 2-stage reduce).
// grid (16 chunks, NH heads), 256 threads, one row per thread.
// ============================================================
__global__ __launch_bounds__(256)
void norm_partial()
{
    const int c   = blockIdx.x;
    const int h   = blockIdx.y;
    const int tid = threadIdx.x;
    const int bt  = c * 256 + tid;          // 0..4095
    const int b   = bt >> 11;
    const int t   = bt & 2047;

    const float* row = g_O + (size_t)((b * NH + h) * SEQ + t) * HD;
    float ss = 0.f;
    #pragma unroll
    for (int i = 0; i < 16; i++) {
        float4 v = *(const float4*)&row[i * 4];
        ss += v.x * v.x + v.y * v.y + v.z * v.z + v.w * v.w;
    }
    float nrm = sqrtf(ss);

    __shared__ float red[256];
    red[tid] = nrm;
    __syncthreads();
    for (int s = 128; s > 0; s >>= 1) {
        if (tid < s) red[tid] += red[tid + s];
        __syncthreads();
    }
    if (tid == 0) g_partial[h * 16 + c] = red[0];
}

// ============================================================
// Kernel 4: finalize per-head scale g/(denom*H) and fused output bias.
// ============================================================
__global__ void finalize(const float* __restrict__ gate,
                         const float* __restrict__ b_o)
{
    const int tid = threadIdx.x;   // 1024 threads
    if (tid < NH) {
        float s = 0.f;
        #pragma unroll
        for (int c = 0; c < 16; c++) s += g_partial[tid * 16 + c];
        float denom = fmaxf(s / (float)MROWS, 1e-5f);
        float g = fminf(fmaxf(gate[tid], 0.f), 1.f);
        g_scale[tid] = g / (denom * (float)NH);
    }
    float bsum = 0.f;
    #pragma unroll
    for (int h = 0; h < NH; h++) {
        float g = fminf(fmaxf(gate[h], 0.f), 1.f);
        bsum += g * b_o[h * EMB + tid];
    }
    g_bias[tid] = bsum / (float)NH;
}

// ============================================================
// Kernel 5: output projection GEMM.
// A[r,k=(h,e)] = g_O[b,h,t,e] * g_scale[h];  B = W_o linear [1024,1024];
// C = d_out[r,d] + g_bias[d].
// ============================================================
__global__ __launch_bounds__(256)
void out_gemm(const float* __restrict__ Wo, float* __restrict__ OUTP)
{
    __shared__ float As[16][128];
    __shared__ float Bs[16][128];

    const int m0  = blockIdx.y * 128;
    const int n0  = blockIdx.x * 128;
    const int tid = threadIdx.x;
    const int tx  = tid & 15;
    const int ty  = tid >> 4;

    float acc[8][8];
    #pragma unroll
    for (int i = 0; i < 8; i++)
        #pragma unroll
        for (int j = 0; j < 8; j++) acc[i][j] = 0.f;

    for (int k0 = 0; k0 < EMB; k0 += 16) {
        // A tile with remap + per-head scale
        #pragma unroll
        for (int i = 0; i < 2; i++) {
            int f    = tid + i * 256;
            int arow = f >> 2;
            int ac   = (f & 3) * 4;
            int r    = m0 + arow;
            int k    = k0 + ac;
            int hh   = k >> 6;
            float s  = g_scale[hh];
            const float* src = &g_O[(size_t)(((r >> 11) * NH + hh) * SEQ + (r & 2047)) * HD + (k & 63)];
            float4 v = *(const float4*)src;
            As[ac + 0][arow] = v.x * s;
            As[ac + 1][arow] = v.y * s;
            As[ac + 2][arow] = v.z * s;
            As[ac + 3][arow] = v.w * s;
        }
        // B tile: W_o is [H,hd,E] = linear [k,d]
        #pragma unroll
        for (int i = 0; i < 2; i++) {
            int f    = tid + i * 256;
            int brow = f >> 5;
            int bc   = (f & 31) * 4;
            float4 v = *(const float4*)&Wo[(size_t)(k0 + brow) * EMB + n0 + bc];
            *(float4*)&Bs[brow][bc] = v;
        }
        __syncthreads();

        #pragma unroll
        for (int k = 0; k < 16; k++) {
            float a[8], b[8];
            #pragma unroll
            for (int i = 0; i < 4; i++) {
                a[i]     = As[k][ty * 4 + i];
                a[i + 4] = As[k][64 + ty * 4 + i];
                b[i]     = Bs[k][tx * 4 + i];
                b[i + 4] = Bs[k][64 + tx * 4 + i];
            }
            #pragma unroll
            for (int i = 0; i < 8; i++)
                #pragma unroll
                for (int j = 0; j < 8; j++)
                    acc[i][j] += a[i] * b[j];
        }
        __syncthreads();
    }

    #pragma unroll
    for (int i = 0; i < 8; i++) {
        int r = m0 + ((i < 4) ? (ty * 4 + i) : (64 + ty * 4 + (i - 4)));
        #pragma unroll
        for (int j = 0; j < 8; j++) {
            int c = n0 + ((j < 4) ? (tx * 4 + j) : (64 + tx * 4 + (j - 4)));
            OUTP[(size_t)r * EMB + c] = acc[i][j] + g_bias[c];
        }
    }
}

// ============================================================
extern "C" void kernel_launch(void* const* d_in, const int* in_sizes, int n_in,
                              void* d_out, int out_size)
{
    const float* X    = (const float*)d_in[0];
    const float* mask = (const float*)d_in[1];
    const float* Wq   = (const float*)d_in[2];
    const float* bq   = (const float*)d_in[3];
    const float* Wk   = (const float*)d_in[4];
    const float* bk   = (const float*)d_in[5];
    const float* Wv   = (const float*)d_in[6];
    const float* bv   = (const float*)d_in[7];
    const float* Wo   = (const float*)d_in[8];
    const float* bo   = (const float*)d_in[9];
    const float* gate = (const float*)d_in[10];
    float* out        = (float*)d_out;

    qkv_gemm   <<<dim3(EMB / 128, MROWS / 128, 3), 256>>>(X, Wq, bq, Wk, bk, Wv, bv);
    attn_kernel<<<dim3(SEQ / 64, NH, BATCH),       256>>>(mask);
    norm_partial<<<dim3(16, NH),                   256>>>();
    finalize   <<<1, EMB>>>(gate, bo);
    out_gemm   <<<dim3(EMB / 128, MROWS / 128),    256>>>(Wo, out);
}